// round 12
// baseline (speedup 1.0000x reference)
#include <cuda_runtime.h>
#include <cstdint>
#include <cstddef>

// out[t, n*16+f] = relu(bias[f] + sum_{j=0..31} x[t-2j-1, n] * w_pn[j][f])
// w_pn = per-filter l2-normalized relu(weights); rows t-2j-1 < 0 contribute 0.
//
// R7 winner + two surgical changes:
//  - warp tile 8t x 8f (f-split across warp pairs): weight LDS per j: 8 -> 2
//    (LDS.128), 16 FMAs per LDS byte-wise -> crossbar/issue relief.
//  - register double-buffered weights: step j prefetches j+1's 4 pairs ->
//    LDS->use distance = one full j-step (~70cyc) >> 29cyc LDS latency.
// x path unchanged: group-of-4 lag batching with 8-row LDG prefetch, __stcs
// streaming stores. Thread tile: 1 n x 8 t x 8 f, f-paired f32x2 accumulators.

#define T_DIM 2048
#define N_DIM 4096
#define L_DIM 32
#define F_DIM 16
#define OUTW  (N_DIM * F_DIM)

using ull = unsigned long long;

__device__ __forceinline__ ull dup2(float v) {
    ull r;
    unsigned u = __float_as_uint(v);
    asm("mov.b64 %0, {%1, %1};" : "=l"(r) : "r"(u));
    return r;
}

__device__ __forceinline__ void fma2(ull& d, ull a, ull b) {
    asm("fma.rn.f32x2 %0, %1, %2, %0;" : "+l"(d) : "l"(a), "l"(b));
}

__device__ __forceinline__ float2 unpack2(ull v) {
    float2 r;
    asm("mov.b64 {%0, %1}, %2;" : "=f"(r.x), "=f"(r.y) : "l"(v));
    return r;
}

// x[t0 + off, n]: off is a compile-time literal -> [base + imm] addressing.
template<bool GUARD>
__device__ __forceinline__ float ldrow(const float* __restrict__ p, int t0, int off) {
    if (GUARD && (t0 + off < 0)) return 0.0f;
    return __ldg(p + (ptrdiff_t)off * N_DIM);
}

// Warp tile: 1 n-lane x 8 consecutive t x 8 filters (fg*8 .. fg*8+7).
template<bool GUARD>
__device__ __forceinline__ void compute_tile(
    const float* __restrict__ xt,    // x + t0*N + n
    float* __restrict__ op,          // out + t0*OUTW + n*16 + fg*8
    const float* __restrict__ sw,    // smem normalized weights [32][16]
    const float* __restrict__ sb,    // smem biases [16]
    int t0, int fg)
{
    // acc[t][q] = {out[t0+t, fg*8+2q], out[t0+t, fg*8+2q+1]} pre-relu
    ull acc[8][4];
    {
        const ull* sb2 = reinterpret_cast<const ull*>(sb) + fg * 4;
#pragma unroll
        for (int q = 0; q < 4; ++q) {
            ull b = sb2[q];
#pragma unroll
            for (int t = 0; t < 8; ++t) acc[t][q] = b;
        }
    }

    // weight rows as 16B chunks: row j = 4 x ulonglong2, this warp uses 2.
    const ulonglong2* wsrc = reinterpret_cast<const ulonglong2*>(sw) + fg * 2;

    // double-buffered weight pairs; wq[j&1] holds lag j's 4 filter-pairs
    ull wq[2][4];
    {
        ulonglong2 a = wsrc[0];
        ulonglong2 b = wsrc[1];
        wq[0][0] = a.x; wq[0][1] = a.y; wq[0][2] = b.x; wq[0][3] = b.y;
    }

    // Window entering group g (j0=4g): win[k] = x[t0 - 2*j0 - 7 + k], k=0..13.
    // Lag j0+d (d=0..3) needs rows win[6-2d .. 13-2d].
    float win[14];
#pragma unroll
    for (int k = 0; k < 14; ++k)
        win[k] = ldrow<GUARD>(xt, t0, -7 + k);

#pragma unroll
    for (int g = 0; g < 8; ++g) {
        // batch-prefetch next group's 8 rows (MLP=8, distance ~4 j-steps)
        float nbuf[8];
        if (g < 7) {
#pragma unroll
            for (int k = 0; k < 8; ++k)
                nbuf[k] = ldrow<GUARD>(xt, t0, -8 * g - 15 + k);
        }

#pragma unroll
        for (int d = 0; d < 4; ++d) {
            const int j   = 4 * g + d;
            const int cur = j & 1;
            const int nxt = cur ^ 1;

            // prefetch next lag's weights into the alternate buffer
            if (j < L_DIM - 1) {
                ulonglong2 a = wsrc[(j + 1) * 4];
                ulonglong2 b = wsrc[(j + 1) * 4 + 1];
                wq[nxt][0] = a.x; wq[nxt][1] = a.y;
                wq[nxt][2] = b.x; wq[nxt][3] = b.y;
            }

            ull xd[8];
#pragma unroll
            for (int t = 0; t < 8; ++t)
                xd[t] = dup2(win[6 - 2 * d + t]);

#pragma unroll
            for (int q = 0; q < 4; ++q) {
                ull w = wq[cur][q];
#pragma unroll
                for (int t = 0; t < 8; ++t)
                    fma2(acc[t][q], xd[t], w);
            }
        }

        // shift window down 8 rows; new base = old base - 8
        if (g < 7) {
#pragma unroll
            for (int k = 13; k >= 8; --k) win[k] = win[k - 8];
#pragma unroll
            for (int k = 0; k < 8; ++k) win[k] = nbuf[k];
        }
    }

    // relu + streaming stores: 8 contiguous floats per t = 2x STG.128.
    // Adjacent q-pairs are adjacent filters -> direct float4 assembly.
#pragma unroll
    for (int t = 0; t < 8; ++t) {
        float4* dst = reinterpret_cast<float4*>(op + (size_t)t * OUTW);
        float2 a0 = unpack2(acc[t][0]);
        float2 a1 = unpack2(acc[t][1]);
        float2 a2 = unpack2(acc[t][2]);
        float2 a3 = unpack2(acc[t][3]);
        float4 v0, v1;
        v0.x = fmaxf(a0.x, 0.0f); v0.y = fmaxf(a0.y, 0.0f);
        v0.z = fmaxf(a1.x, 0.0f); v0.w = fmaxf(a1.y, 0.0f);
        v1.x = fmaxf(a2.x, 0.0f); v1.y = fmaxf(a2.y, 0.0f);
        v1.z = fmaxf(a3.x, 0.0f); v1.w = fmaxf(a3.y, 0.0f);
        __stcs(dst + 0, v0);
        __stcs(dst + 1, v1);
    }
}

__global__ void __launch_bounds__(256, 2)
tlayer_kernel(const float* __restrict__ x,
              const float* __restrict__ W,
              const float* __restrict__ B,
              float* __restrict__ out)
{
    __shared__ __align__(16) float sw[L_DIM * F_DIM];  // normalized weights [j][f]
    __shared__ __align__(16) float sb[F_DIM];

    const int tid = threadIdx.x;

    // weight prep: relu + per-filter l2 normalize (matches reference)
    if (tid < F_DIM) {
        float ss = 0.0f;
        for (int j = 0; j < L_DIM; ++j) {
            float wv = fmaxf(__ldg(W + j * F_DIM + tid), 0.0f);
            ss += wv * wv;
        }
        float inv = rsqrtf(fmaxf(ss, 1e-12f));
        for (int j = 0; j < L_DIM; ++j) {
            sw[j * F_DIM + tid] = fmaxf(__ldg(W + j * F_DIM + tid), 0.0f) * inv;
        }
        sb[tid] = __ldg(B + tid);
    }
    __syncthreads();

    const int lane = tid & 31;
    const int warp = tid >> 5;
    const int tg   = warp >> 1;      // 4 t-groups of 8
    const int fg   = warp & 1;       // 2 filter-halves

    const int n  = blockIdx.x * 32 + lane;        // 128 n-blocks
    const int t0 = blockIdx.y * 32 + tg * 8;      // 64 t-blocks, 32 t per block

    const float* xt = x + (size_t)t0 * N_DIM + n;
    float*       op = out + (size_t)t0 * OUTW + (size_t)n * F_DIM + fg * 8;

    // deepest row touched is t0 - 63; guard only the first t-blocks
    if (t0 >= 63) {
        compute_tile<false>(xt, op, sw, sb, t0, fg);
    } else {
        compute_tile<true>(xt, op, sw, sb, t0, fg);
    }
}

extern "C" void kernel_launch(void* const* d_in, const int* in_sizes, int n_in,
                              void* d_out, int out_size) {
    (void)in_sizes; (void)n_in; (void)out_size;
    const float* x = (const float*)d_in[0];   // [2048, 4096]
    const float* W = (const float*)d_in[1];   // [32, 16]
    const float* B = (const float*)d_in[2];   // [16]
    float* out = (float*)d_out;               // [2048, 65536]

    dim3 grid(N_DIM / 32, T_DIM / 32);        // (128, 64)
    tlayer_kernel<<<grid, 256>>>(x, W, B, out);
}

// round 14
// speedup vs baseline: 1.7659x; 1.7659x over previous
#include <cuda_runtime.h>
#include <cuda_bf16.h>
#include <cstdint>
#include <cstddef>

// out[t, n*16+f] = relu(bias[f] + sum_{j=0..31} x[t-1-2j, n] * w_pn[j][f])
// w_pn = per-filter l2-normalized relu(weights); rows t-1-2j < 0 contribute 0.
//
// mma.sync (sm_80 HMMA, plain compute_103 -- NO tcgen05/'a' features):
// per t, warp computes D[16n, 16f] = A[16n, 32j] @ W via 2 ktiles x 2 ftiles
// x 3 precision terms (AhBh + AhBl + AlBh) of m16n8k16 bf16 mma.
//
// x strip (rows t0-63..t0+62) staged once per CTA in smem as bf16 hi/lo,
// parity-split, DESCENDING row order, two alignment-phase copies:
//   parity q, entry e holds row (t0+62-q) - 2e   (e = 0..62)
// For any t, its 32 lag rows are entries e0..e0+31 of one parity array ->
// every A-fragment register is ONE aligned LDS.32 of 2 consecutive lags.
// Pitch 144B = 36 words (36 mod 32 = 4) -> A-load banks 4g+i: conflict-free.
//
// B fragments precomputed in registers with filter permutation
//   f(col, ft) = 4*(col>>1) + 2*ft + (col&1)
// so each thread's 4 output filters are contiguous -> epilogue = 2x STG.128.

#define T_DIM 2048
#define N_DIM 4096
#define OUTW  (N_DIM * 16)

#define PITCHB 144                 // bytes per n-row in strip arrays
#define ARRB   (128 * PITCHB)      // 18432 per (parity, phase) array
#define OFF_SWF 0                  // w_pn fp32 [32][16]
#define OFF_SB  2048               // bias fp32 [16]
#define OFF_HI  2112               // 4 hi arrays: (q<<1)|ph
#define LO_DELTA (4 * ARRB)        // lo arrays at hi + 73728
#define SMEM_TOTAL (OFF_HI + 8 * ARRB)   // 149568 bytes

__device__ __forceinline__ uint32_t smem_u32(const void* p) {
    uint32_t a;
    asm("{ .reg .u64 t; cvta.to.shared.u64 t, %1; cvt.u32.u64 %0, t; }"
        : "=r"(a) : "l"(p));
    return a;
}

template<int IMM>
__device__ __forceinline__ uint32_t lds32(uint32_t base) {
    uint32_t v;
    asm volatile("ld.shared.b32 %0, [%1+%2];" : "=r"(v) : "r"(base), "n"(IMM));
    return v;
}

// pack two f32 -> bf16x2, 'lo' in lower half
__device__ __forceinline__ uint32_t pack2bf(float lo, float hi) {
    uint32_t r;
    asm("cvt.rn.bf16x2.f32 %0, %1, %2;" : "=r"(r) : "f"(hi), "f"(lo));
    return r;
}

// D(16x8,f32) += A(16x16,bf16) @ B(16x8,bf16)
__device__ __forceinline__ void mma8(float* d, const uint32_t* a, const uint32_t* b) {
    asm volatile(
        "mma.sync.aligned.m16n8k16.row.col.f32.bf16.bf16.f32 "
        "{%0,%1,%2,%3}, {%4,%5,%6,%7}, {%8,%9}, {%0,%1,%2,%3};"
        : "+f"(d[0]), "+f"(d[1]), "+f"(d[2]), "+f"(d[3])
        : "r"(a[0]), "r"(a[1]), "r"(a[2]), "r"(a[3]), "r"(b[0]), "r"(b[1]));
}

__global__ void __launch_bounds__(512, 1)
tlayer_mma_kernel(const float* __restrict__ x,
                  const float* __restrict__ Wg,
                  const float* __restrict__ Bg,
                  float* __restrict__ out)
{
    extern __shared__ __align__(16) char smem[];
    float* swf = reinterpret_cast<float*>(smem + OFF_SWF);
    float* sbv = reinterpret_cast<float*>(smem + OFF_SB);

    const int tid  = threadIdx.x;
    const int lane = tid & 31;
    const int wid  = tid >> 5;
    const int n0   = blockIdx.x * 128;
    const int t0   = blockIdx.y * 64;

    // ---- weight prep: relu + per-filter l2 normalize (fp32, matches ref) ----
    if (tid < 16) {
        float ss = 0.0f;
        for (int j = 0; j < 32; ++j) {
            float wv = fmaxf(__ldg(Wg + j * 16 + tid), 0.0f);
            ss += wv * wv;
        }
        float inv = rsqrtf(fmaxf(ss, 1e-12f));
        for (int j = 0; j < 32; ++j)
            swf[j * 16 + tid] = fmaxf(__ldg(Wg + j * 16 + tid), 0.0f) * inv;
        sbv[tid] = __ldg(Bg + tid);
    }

    // ---- stage x strip: 126 rows (t0-63 .. t0+62), hi/lo, 2 phases ----
#pragma unroll
    for (int k = 0; k < 8; ++k) {
        int i = wid + k * 16;
        if (i < 126) {
            int r = t0 - 63 + i;
            int q = r & 1;
            int e = (t0 + 62 - q - r) >> 1;          // 0..62
            char* hi0 = smem + OFF_HI + (q << 1) * ARRB;
            char* hi1 = hi0 + ARRB;
#pragma unroll
            for (int c = 0; c < 4; ++c) {
                int n = lane + 32 * c;
                float v = (r >= 0) ? __ldg(x + (size_t)r * N_DIM + n0 + n) : 0.0f;
                __nv_bfloat16 h = __float2bfloat16(v);
                __nv_bfloat16 l = __float2bfloat16(v - __bfloat162float(h));
                int ro = n * PITCHB;
                *reinterpret_cast<__nv_bfloat16*>(hi0 + ro + e * 2)            = h;
                *reinterpret_cast<__nv_bfloat16*>(hi0 + LO_DELTA + ro + e * 2) = l;
                if (e > 0) {
                    *reinterpret_cast<__nv_bfloat16*>(hi1 + ro + (e - 1) * 2)            = h;
                    *reinterpret_cast<__nv_bfloat16*>(hi1 + LO_DELTA + ro + (e - 1) * 2) = l;
                }
            }
        }
    }
    __syncthreads();

    const int g  = lane >> 2;      // fragment row group
    const int qi = lane & 3;       // fragment col group
    const int wn = wid & 7;        // n-block (16 n)
    const int wt = wid >> 3;       // t-half (32 t)

    // ---- B fragments in registers: [ktile][ftile][b0/b1], hi + lo ----
    uint32_t Bh[2][2][2], Bl[2][2][2];
    {
        int f = 4 * (g >> 1) + (g & 1);  // + 2*ft below
#pragma unroll
        for (int ft = 0; ft < 2; ++ft) {
#pragma unroll
            for (int kt = 0; kt < 2; ++kt) {
#pragma unroll
                for (int hb = 0; hb < 2; ++hb) {
                    int kk = kt * 16 + 2 * qi + hb * 8;
                    float w0 = swf[kk * 16 + f + 2 * ft];
                    float w1 = swf[(kk + 1) * 16 + f + 2 * ft];
                    float h0 = __bfloat162float(__float2bfloat16(w0));
                    float h1 = __bfloat162float(__float2bfloat16(w1));
                    Bh[kt][ft][hb] = pack2bf(w0, w1);
                    Bl[kt][ft][hb] = pack2bf(w0 - h0, w1 - h1);
                }
            }
        }
    }
    const float bias0 = sbv[4 * qi + 0], bias1 = sbv[4 * qi + 1];
    const float bias2 = sbv[4 * qi + 2], bias3 = sbv[4 * qi + 3];

    const int nl = wn * 16 + g;
    const uint32_t hib = smem_u32(smem) + OFF_HI + nl * PITCHB + 4 * qi;
    float* outb = out + (size_t)(n0 + nl) * 16 + 4 * qi;

    // ---- main loop: 32 t per warp ----
    for (int tt = 0; tt < 32; ++tt) {
        const int t  = t0 + wt * 32 + tt;
        const int q  = (t - 1) & 1;                    // parity of lag rows
        const int e0 = (t0 + 63 - q - t) >> 1;         // window start entry
        const int ph = e0 & 1;
        const uint32_t b0 = hib + (uint32_t)(((q << 1) | ph) * ARRB + (e0 - ph) * 2);
        const uint32_t b1 = b0 + 8 * PITCHB;

        // A fragments: [0..3] = ktile0 (j 0..15), [4..7] = ktile1 (j 16..31)
        uint32_t Ah[8], Al[8];
        Ah[0] = lds32<0>(b0);   Ah[1] = lds32<0>(b1);
        Ah[2] = lds32<16>(b0);  Ah[3] = lds32<16>(b1);
        Ah[4] = lds32<32>(b0);  Ah[5] = lds32<32>(b1);
        Ah[6] = lds32<48>(b0);  Ah[7] = lds32<48>(b1);
        Al[0] = lds32<LO_DELTA + 0>(b0);   Al[1] = lds32<LO_DELTA + 0>(b1);
        Al[2] = lds32<LO_DELTA + 16>(b0);  Al[3] = lds32<LO_DELTA + 16>(b1);
        Al[4] = lds32<LO_DELTA + 32>(b0);  Al[5] = lds32<LO_DELTA + 32>(b1);
        Al[6] = lds32<LO_DELTA + 48>(b0);  Al[7] = lds32<LO_DELTA + 48>(b1);

        float d0[4] = {bias0, bias1, bias0, bias1};    // ftile0
        float d1[4] = {bias2, bias3, bias2, bias3};    // ftile1

        // 12 mma, two independent chains (d0 / d1) interleaved
        mma8(d0, Ah + 0, Bh[0][0]);  mma8(d1, Ah + 0, Bh[0][1]);
        mma8(d0, Ah + 4, Bh[1][0]);  mma8(d1, Ah + 4, Bh[1][1]);
        mma8(d0, Ah + 0, Bl[0][0]);  mma8(d1, Ah + 0, Bl[0][1]);
        mma8(d0, Ah + 4, Bl[1][0]);  mma8(d1, Ah + 4, Bl[1][1]);
        mma8(d0, Al + 0, Bh[0][0]);  mma8(d1, Al + 0, Bh[0][1]);
        mma8(d0, Al + 4, Bh[1][0]);  mma8(d1, Al + 4, Bh[1][1]);

        // relu + store: thread's filters are contiguous (4qi..4qi+3)
        float4 v0, v1;
        v0.x = fmaxf(d0[0], 0.0f); v0.y = fmaxf(d0[1], 0.0f);
        v0.z = fmaxf(d1[0], 0.0f); v0.w = fmaxf(d1[1], 0.0f);
        v1.x = fmaxf(d0[2], 0.0f); v1.y = fmaxf(d0[3], 0.0f);
        v1.z = fmaxf(d1[2], 0.0f); v1.w = fmaxf(d1[3], 0.0f);
        float* dst = outb + (size_t)t * OUTW;
        __stcs(reinterpret_cast<float4*>(dst), v0);          // n = nl
        __stcs(reinterpret_cast<float4*>(dst + 128), v1);    // n = nl + 8
    }
}

extern "C" void kernel_launch(void* const* d_in, const int* in_sizes, int n_in,
                              void* d_out, int out_size) {
    (void)in_sizes; (void)n_in; (void)out_size;
    const float* x = (const float*)d_in[0];   // [2048, 4096]
    const float* W = (const float*)d_in[1];   // [32, 16]
    const float* B = (const float*)d_in[2];   // [16]
    float* out = (float*)d_out;               // [2048, 65536]

    cudaFuncSetAttribute(tlayer_mma_kernel,
                         cudaFuncAttributeMaxDynamicSharedMemorySize, SMEM_TOTAL);
    dim3 grid(N_DIM / 128, T_DIM / 64);       // (32, 32)
    tlayer_mma_kernel<<<grid, 512, SMEM_TOTAL>>>(x, W, B, out);
}